// round 14
// baseline (speedup 1.0000x reference)
#include <cuda_runtime.h>
#include <cstdint>
#include <cstddef>

// Problem constants
#define BSZ 256      // batch
#define TT  512      // time steps
#define EE  256      // input dim
#define HH  256      // hidden dim
#define NB  4        // batches per cluster

// Skewed h layout: quarter kq of each batch-row starts at kq*68 floats
// (68 = 64 + 4 pad -> quarters start on banks 0/4/8/12: the 4 kq-streams
// read by adjacent lanes are conflict-free). Row size 4*68 = 272 floats.
#define QSK   68
#define BROW  (4 * QSK)          // 272 floats per (batch) row
#define PBUF  (NB * BROW)        // 1088 floats per ping-pong buffer

typedef unsigned long long ull;

// ---- packed f32x2 helpers (Blackwell) -------------------------------------
__device__ __forceinline__ ull fma2(ull a, ull b, ull c) {
    ull d;
    asm("fma.rn.f32x2 %0, %1, %2, %3;" : "=l"(d) : "l"(a), "l"(b), "l"(c));
    return d;
}
__device__ __forceinline__ ull splat2(float x) {
    ull d;
    asm("mov.b64 %0, {%1, %1};" : "=l"(d) : "f"(x));
    return d;
}
__device__ __forceinline__ float2 unpack2(ull a) {
    float2 r;
    asm("mov.b64 {%0, %1}, %2;" : "=f"(r.x), "=f"(r.y) : "l"(a));
    return r;
}
__device__ __forceinline__ uint32_t smem_u32(const void* p) {
    uint32_t a;
    asm("{ .reg .u64 t; cvta.to.shared.u64 t, %1; cvt.u32.u64 %0, t; }"
        : "=r"(a) : "l"(p));
    return a;
}

// ---- one-MUFU transcendentals ([1,2] reciprocal seed) ----------------------
__device__ __forceinline__ float rcp_1to2(float d) {
    float r = fmaf(d, -0.47058824f, 1.4117647f);  // 24/17 - 8/17*d
    r = r * fmaf(-d, r, 2.0f);
    r = r * fmaf(-d, r, 2.0f);                    // err ~1.2e-5
    return r;
}
__device__ __forceinline__ float ftanh(float z) {
    const float az = fabsf(z);
    const float e = __expf(-2.0f * az);           // 1 MUFU
    const float r = rcp_1to2(1.0f + e);
    const float t = (1.0f - e) * r;
    return copysignf(t, z);
}
__device__ __forceinline__ float fsigmoid(float z) {
    const float az = fabsf(z);
    const float e = __expf(-az);                  // 1 MUFU
    const float r = rcp_1to2(1.0f + e);
    return (z >= 0.0f) ? r : e * r;
}

// ---------------------------------------------------------------------------
// Phase 1: gates = sigmoid(X @ Wx^T + b)  via packed-f32x2 SGEMM. (unchanged)
// ---------------------------------------------------------------------------
__global__ __launch_bounds__(256, 2) void gates_kernel(
    const float* __restrict__ X, const float* __restrict__ W,
    const float* __restrict__ bias, float* __restrict__ G)
{
    __shared__ __align__(16) float As[16][128];
    __shared__ __align__(16) float Ws[16][128];

    const int tid = threadIdx.x;
    const int bm = blockIdx.x * 128;
    const int bn = blockIdx.y * 128;
    const int tx = tid & 15;
    const int ty = tid >> 4;
    const int lr = tid >> 2;
    const int lc = (tid & 3) << 2;

    ull acc[8][4];
#pragma unroll
    for (int i = 0; i < 8; ++i)
#pragma unroll
        for (int jj = 0; jj < 4; ++jj) acc[i][jj] = 0ull;

    const float* Xp0 = X + (size_t)(bm + lr) * EE + lc;
    const float* Xp1 = X + (size_t)(bm + lr + 64) * EE + lc;
    const float* Wp0 = W + (size_t)(bn + lr) * EE + lc;
    const float* Wp1 = W + (size_t)(bn + lr + 64) * EE + lc;

    float4 pa0 = *(const float4*)(Xp0);
    float4 pa1 = *(const float4*)(Xp1);
    float4 pw0 = *(const float4*)(Wp0);
    float4 pw1 = *(const float4*)(Wp1);

#pragma unroll 1
    for (int k0 = 0; k0 < EE; k0 += 16) {
        __syncthreads();
        As[lc + 0][lr] = pa0.x; As[lc + 1][lr] = pa0.y;
        As[lc + 2][lr] = pa0.z; As[lc + 3][lr] = pa0.w;
        As[lc + 0][lr + 64] = pa1.x; As[lc + 1][lr + 64] = pa1.y;
        As[lc + 2][lr + 64] = pa1.z; As[lc + 3][lr + 64] = pa1.w;
        Ws[lc + 0][lr] = pw0.x; Ws[lc + 1][lr] = pw0.y;
        Ws[lc + 2][lr] = pw0.z; Ws[lc + 3][lr] = pw0.w;
        Ws[lc + 0][lr + 64] = pw1.x; Ws[lc + 1][lr + 64] = pw1.y;
        Ws[lc + 2][lr + 64] = pw1.z; Ws[lc + 3][lr + 64] = pw1.w;
        __syncthreads();

        if (k0 + 16 < EE) {
            pa0 = *(const float4*)(Xp0 + k0 + 16);
            pa1 = *(const float4*)(Xp1 + k0 + 16);
            pw0 = *(const float4*)(Wp0 + k0 + 16);
            pw1 = *(const float4*)(Wp1 + k0 + 16);
        }

#pragma unroll
        for (int k = 0; k < 16; ++k) {
            float a[8];
            *(float4*)&a[0] = *(const float4*)&As[k][ty * 8];
            *(float4*)&a[4] = *(const float4*)&As[k][ty * 8 + 4];
            ulonglong2 u0 = *(const ulonglong2*)&Ws[k][tx * 8];
            ulonglong2 u1 = *(const ulonglong2*)&Ws[k][tx * 8 + 4];
            const ull b0 = u0.x, b1 = u0.y, b2 = u1.x, b3 = u1.y;
#pragma unroll
            for (int i = 0; i < 8; ++i) {
                const ull s = splat2(a[i]);
                acc[i][0] = fma2(s, b0, acc[i][0]);
                acc[i][1] = fma2(s, b1, acc[i][1]);
                acc[i][2] = fma2(s, b2, acc[i][2]);
                acc[i][3] = fma2(s, b3, acc[i][3]);
            }
        }
    }

    float bb[8];
#pragma unroll
    for (int jj = 0; jj < 8; ++jj) bb[jj] = bias[bn + tx * 8 + jj];

#pragma unroll
    for (int i = 0; i < 8; ++i) {
        const size_t m = bm + ty * 8 + i;
        float v[8];
#pragma unroll
        for (int jj = 0; jj < 4; ++jj) {
            float2 z = unpack2(acc[i][jj]);
            v[2 * jj]     = fsigmoid(z.x + bb[2 * jj]);
            v[2 * jj + 1] = fsigmoid(z.y + bb[2 * jj + 1]);
        }
        float4 o0 = {v[0], v[1], v[2], v[3]};
        float4 o1 = {v[4], v[5], v[6], v[7]};
        *(float4*)(G + m * HH + bn + tx * 8)     = o0;
        *(float4*)(G + m * HH + bn + tx * 8 + 4) = o1;
    }
}

// ---------------------------------------------------------------------------
// Phase 2: MGU recurrence — in-warp K-quarter reduce (no psum, no BAR1).
//   Cluster(2) x 64, NB=4, 512 steps. CTA rank r owns rows [r*128,+128).
//   256 threads: warp w, lane l; kq = l&3 (K-quarter IN-WARP), row group
//   gidx = w*8 + (l>>2); rows jg0 = r*128+gidx, jg1 = jg0+64.
//   Thread W: rows jg0/jg1 x quarter kq = 64 packed ull (as R13).
//   h layout skewed: (b, j) at b*BROW + (j>>6)*QSK + (j&63); the 4 kq
//   streams read by adjacent lanes start on banks 0/4/8/12 -> conflict-free.
//   Per step: ALL warps wait mb[p] (peer arrive was posted mid-step t-1,
//   mostly fast-path) -> matvec -> 2x shfl_xor butterfly (replaces psum +
//   BAR1) -> lane kq finalizes e in {2kq,2kq+1}: 2 tanh, h_prev in REGS ->
//   2x st.cluster + 2x STS + syncwarp + lane0 remote arrive (count-8 mb,
//   proven R13 protocol) -> 2x STG -> single BAR (orders local h stores).
//   WAR: identical transitive argument to R13 (all 8 peer-warp arrivals are
//   posted after that warp's matvec reads; we wait for count 8).
// ---------------------------------------------------------------------------
__global__ void __cluster_dims__(2, 1, 1) __launch_bounds__(256, 1)
mgu_scan(const float* __restrict__ Whw, const float* __restrict__ Whb,
         float* out)
{
    __shared__ __align__(16) float hsh[2 * PBUF];   // 8.7 KB ping-pong h
    __shared__ __align__(8)  ull  bars[2];

    const int tid = threadIdx.x;
    const int lane = tid & 31;
    const int kq = lane & 3;                 // K-quarter (in-warp)
    const int gidx = (tid >> 5) * 8 + (lane >> 2);   // 0..63 row group
    uint32_t rank;
    asm("mov.u32 %0, %%cluster_ctarank;" : "=r"(rank));
    const int jg0 = (int)rank * 128 + gidx;
    const int jg1 = jg0 + 64;
    const int bbase = (blockIdx.x >> 1) * NB;

    // --- W rows (2 j, this K quarter) into 64 packed registers ---
    ull wv0[32], wv1[32];
    {
        const ulonglong2* wp0 =
            (const ulonglong2*)(Whw + (size_t)jg0 * HH + kq * 64);
        const ulonglong2* wp1 =
            (const ulonglong2*)(Whw + (size_t)jg1 * HH + kq * 64);
#pragma unroll
        for (int i = 0; i < 16; ++i) {
            ulonglong2 a = wp0[i], b = wp1[i];
            wv0[2 * i] = a.x; wv0[2 * i + 1] = a.y;
            wv1[2 * i] = b.x; wv1[2 * i + 1] = b.y;
        }
    }

    for (int i = tid; i < 2 * PBUF; i += 256) hsh[i] = 0.0f;

    if (tid == 0) {
        asm volatile("mbarrier.init.shared.b64 [%0], 8;"
                     :: "r"(smem_u32(&bars[0])) : "memory");
        asm volatile("mbarrier.init.shared.b64 [%0], 8;"
                     :: "r"(smem_u32(&bars[1])) : "memory");
    }

    // ---- ownership: lane kq finalizes e0 = 2kq, e0+1 (e = rowhalf*4 + b) --
    const int jrow = (kq >> 1) ? jg1 : jg0;
    const int b0 = (2 * kq) & 3;             // batches b0, b0+1
    const float biasr = Whb[jrow];

    // out pointers for the 2 owned (batch,row) streams
    float* po0 = out + (size_t)(bbase + b0)     * TT * HH + jrow;
    float* po1 = out + (size_t)(bbase + b0 + 1) * TT * HH + jrow;

    float gc0 = po0[0], gc1 = po1[0];        // gates t=0
    float hc0 = 0.0f, hc1 = 0.0f;            // persistent h (register!)

    // h store offset for (b, jrow): b*BROW + (jrow>>6)*QSK + (jrow&63)
    const int hoff = (jrow >> 6) * QSK + (jrow & 63);

    // cluster addresses
    const uint32_t hl = smem_u32(hsh);
    const uint32_t bl0 = smem_u32(&bars[0]);
    uint32_t hr, br0;
    asm("mapa.shared::cluster.u32 %0, %1, %2;"
        : "=r"(hr) : "r"(hl), "r"(rank ^ 1u));
    asm("mapa.shared::cluster.u32 %0, %1, %2;"
        : "=r"(br0) : "r"(bl0), "r"(rank ^ 1u));

    const bool lane0 = (lane == 0);

    __syncthreads();
    // one-time: both CTAs' smem init + mbarrier init visible cluster-wide
    asm volatile("barrier.cluster.arrive.aligned;" ::: "memory");
    asm volatile("barrier.cluster.wait.aligned;"   ::: "memory");

    uint32_t ph0 = 0, ph1 = 0;
    const unsigned FULL = 0xffffffffu;

#pragma unroll 1
    for (int t = 0; t < TT; ++t) {
        const int p = t & 1;
        const int q = p ^ 1;
        const bool not_last = (t + 1 < TT);

        // prefetch gates for t+1 (issued before any waiting)
        float gn0 = 0.f, gn1 = 0.f;
        if (not_last) {
            const size_t o = (size_t)(t + 1) * HH;
            gn0 = po0[o]; gn1 = po1[o];
        }

        // step barrier: wait for peer's 8 warp-arrivals into buffer p
        if (t > 0) {
            const uint32_t mb = bl0 + (uint32_t)p * 8u;
            const uint32_t par = p ? ph1 : ph0;
            uint32_t done;
            do {
                asm volatile(
                    "{\n\t.reg .pred P;\n\t"
                    "mbarrier.try_wait.parity.acquire.cluster.shared::cta.b64 "
                    "P, [%1], %2, 0x989680;\n\t"
                    "selp.b32 %0, 1, 0, P;\n\t}"
                    : "=r"(done) : "r"(mb), "r"(par) : "memory");
            } while (!done);
            if (p) ph1 ^= 1; else ph0 ^= 1;
        }

        // ---- matvec over this thread's K-quarter (skewed layout) ----
        const float* hb = hsh + p * PBUF + kq * QSK;
        const ulonglong2* x0 = (const ulonglong2*)(hb);
        const ulonglong2* x1 = (const ulonglong2*)(hb + BROW);
        const ulonglong2* x2 = (const ulonglong2*)(hb + 2 * BROW);
        const ulonglong2* x3 = (const ulonglong2*)(hb + 3 * BROW);
        ull a00 = 0, a01 = 0, a02 = 0, a03 = 0;   // row jg0, batches 0..3
        ull a10 = 0, a11 = 0, a12 = 0, a13 = 0;   // row jg1
#pragma unroll
        for (int i = 0; i < 16; ++i) {
            const ulonglong2 v0 = x0[i];
            const ulonglong2 v1 = x1[i];
            const ulonglong2 v2 = x2[i];
            const ulonglong2 v3 = x3[i];
            const ull wA0 = wv0[2 * i], wB0 = wv0[2 * i + 1];
            const ull wA1 = wv1[2 * i], wB1 = wv1[2 * i + 1];
            a00 = fma2(wA0, v0.x, a00); a01 = fma2(wA0, v1.x, a01);
            a02 = fma2(wA0, v2.x, a02); a03 = fma2(wA0, v3.x, a03);
            a10 = fma2(wA1, v0.x, a10); a11 = fma2(wA1, v1.x, a11);
            a12 = fma2(wA1, v2.x, a12); a13 = fma2(wA1, v3.x, a13);
            a00 = fma2(wB0, v0.y, a00); a01 = fma2(wB0, v1.y, a01);
            a02 = fma2(wB0, v2.y, a02); a03 = fma2(wB0, v3.y, a03);
            a10 = fma2(wB1, v0.y, a10); a11 = fma2(wB1, v1.y, a11);
            a12 = fma2(wB1, v2.y, a12); a13 = fma2(wB1, v3.y, a13);
        }

        // pair-sum, then 4-lane butterfly reduce (replaces psum + BAR1)
        float r[8];
        {
            float2 u;
            u = unpack2(a00); r[0] = u.x + u.y;
            u = unpack2(a01); r[1] = u.x + u.y;
            u = unpack2(a02); r[2] = u.x + u.y;
            u = unpack2(a03); r[3] = u.x + u.y;
            u = unpack2(a10); r[4] = u.x + u.y;
            u = unpack2(a11); r[5] = u.x + u.y;
            u = unpack2(a12); r[6] = u.x + u.y;
            u = unpack2(a13); r[7] = u.x + u.y;
        }
#pragma unroll
        for (int e = 0; e < 8; ++e) {
            r[e] += __shfl_xor_sync(FULL, r[e], 1);
            r[e] += __shfl_xor_sync(FULL, r[e], 2);
        }

        // ---- lane kq finalizes its 2 owned streams ----
        const float zA = ((kq == 0) ? r[0] : (kq == 1) ? r[2]
                         : (kq == 2) ? r[4] : r[6]) + biasr;
        const float zB = ((kq == 0) ? r[1] : (kq == 1) ? r[3]
                         : (kq == 2) ? r[5] : r[7]) + biasr;
        const float thA = ftanh(zA);
        const float thB = ftanh(zB);
        hc0 = fmaf(gc0, hc0 - thA, thA);    // g*h + (1-g)*tanh
        hc1 = fmaf(gc1, hc1 - thB, thB);
        gc0 = gn0; gc1 = gn1;

        if (not_last) {
            const int base = q * PBUF + hoff;
            // peer DSMEM stores first (longest flight)
            const uint32_t ra0 = hr + (uint32_t)(base + b0 * BROW) * 4u;
            asm volatile("st.shared::cluster.f32 [%0], %1;"
                         :: "r"(ra0), "f"(hc0) : "memory");
            asm volatile("st.shared::cluster.f32 [%0], %1;"
                         :: "r"(ra0 + (uint32_t)(BROW * 4)), "f"(hc1)
                         : "memory");
            hsh[base + b0 * BROW]       = hc0;
            hsh[base + (b0 + 1) * BROW] = hc1;
            __syncwarp();
            if (lane0) {
                asm volatile(
                    "mbarrier.arrive.release.cluster.shared::cluster.b64 _, [%0];"
                    :: "r"(br0 + (uint32_t)q * 8u) : "memory");
            }
        }

        // global out stores (gate nothing)
        const size_t ot = (size_t)t * HH;
        po0[ot] = hc0;
        po1[ot] = hc1;

        __syncthreads();   // orders local h stores for next step's readers
    }

    // Trailing cluster sync: no CTA exits while peer DSMEM traffic may be
    // in flight toward it.
    asm volatile("barrier.cluster.arrive.aligned;" ::: "memory");
    asm volatile("barrier.cluster.wait.aligned;"   ::: "memory");
}

// ---------------------------------------------------------------------------
extern "C" void kernel_launch(void* const* d_in, const int* in_sizes, int n_in,
                              void* d_out, int out_size)
{
    const float* x   = (const float*)d_in[0];  // [B,T,E]
    const float* Wxw = (const float*)d_in[1];  // [H,E]
    const float* Wxb = (const float*)d_in[2];  // [H]
    const float* Whw = (const float*)d_in[3];  // [H,H]
    const float* Whb = (const float*)d_in[4];  // [H]
    float* out = (float*)d_out;                // [B,T,H]

    dim3 g1(BSZ * TT / 128, HH / 128);
    gates_kernel<<<g1, 256>>>(x, Wxw, Wxb, out);

    mgu_scan<<<(BSZ / NB) * 2, 256>>>(Whw, Whb, out);
}